// round 4
// baseline (speedup 1.0000x reference)
#include <cuda_runtime.h>

#define MARGIN 0.2f
#define TPB   256
#define TILE  256
#define NWARP (TPB / 32)
#define NB    64
#define MAXN  16384

__device__ double g_rank_sum;
__device__ double g_m[5];        // sum_p, sum_p2, sum_t, sum_t2, sum_diff2
__device__ unsigned int g_done;
__device__ int   g_hist[NB];
__device__ int   g_bstart[NB];
__device__ float g_ps[MAXN];     // predictions, bucket-reordered
__device__ float g_tt[MAXN];     // targets, bucket-reordered

__device__ __forceinline__ int bucket_of(float t) {
    int b = (int)(t * (float)NB);
    return min(NB - 1, max(0, b));
}

// ---------------------------------------------------------------------------
// 0) zero all accumulators (graph-replayed)
// ---------------------------------------------------------------------------
__global__ void init_kernel() {
    int tid = threadIdx.x;
    if (tid < NB) g_hist[tid] = 0;
    if (tid == NB)     g_rank_sum = 0.0;
    if (tid == NB + 1) g_done = 0u;
    if (tid >= NB + 2 && tid < NB + 7) g_m[tid - NB - 2] = 0.0;
}

// ---------------------------------------------------------------------------
// 1) histogram of targets into NB buckets + O(N) moments
// ---------------------------------------------------------------------------
__global__ __launch_bounds__(TPB) void histmom_kernel(const float* __restrict__ pr,
                                                      const float* __restrict__ tg,
                                                      int n) {
    __shared__ int    shist[NB];
    __shared__ double smom[5][NWARP];
    const int tid = threadIdx.x, lane = tid & 31, wid = tid >> 5;

    for (int q = tid; q < NB; q += TPB) shist[q] = 0;
    __syncthreads();

    double m[5] = {0, 0, 0, 0, 0};
    for (int i = blockIdx.x * TPB + tid; i < n; i += gridDim.x * TPB) {
        float p = pr[i], t = tg[i];
        atomicAdd(&shist[bucket_of(t)], 1);
        double pv = (double)p, tv = (double)t, d = pv - tv;
        m[0] += pv; m[1] += pv * pv; m[2] += tv; m[3] += tv * tv; m[4] += d * d;
    }
    #pragma unroll
    for (int q = 0; q < 5; q++) {
        #pragma unroll
        for (int o = 16; o > 0; o >>= 1)
            m[q] += __shfl_down_sync(0xFFFFFFFFu, m[q], o);
        if (lane == 0) smom[q][wid] = m[q];
    }
    __syncthreads();
    if (wid == 0) {
        #pragma unroll
        for (int q = 0; q < 5; q++) {
            double v = (lane < NWARP) ? smom[q][lane] : 0.0;
            #pragma unroll
            for (int o = 4; o > 0; o >>= 1)
                v += __shfl_down_sync(0xFFFFFFFFu, v, o);
            if (lane == 0) atomicAdd(&g_m[q], v);
        }
    }
    __syncthreads();
    for (int q = tid; q < NB; q += TPB)
        if (shist[q]) atomicAdd(&g_hist[q], shist[q]);
}

// ---------------------------------------------------------------------------
// 2) exclusive prefix sum over NB buckets (trivial size)
// ---------------------------------------------------------------------------
__global__ void prefix_kernel() {
    if (threadIdx.x == 0) {
        int s = 0;
        for (int b = 0; b < NB; b++) { g_bstart[b] = s; s += g_hist[b]; }
    }
}

// ---------------------------------------------------------------------------
// 3) deterministic stable scatter: block b collects all elements of bucket b
//    in original index order (ballot-scan ranking).
// ---------------------------------------------------------------------------
__global__ __launch_bounds__(TPB) void scatter_kernel(const float* __restrict__ pr,
                                                      const float* __restrict__ tg,
                                                      int n) {
    __shared__ int swcnt[NWARP];
    const int b = blockIdx.x;
    const int tid = threadIdx.x, lane = tid & 31, wid = tid >> 5;
    const int base = g_bstart[b];
    int running = 0;

    for (int c0 = 0; c0 < n; c0 += TPB) {
        int idx = c0 + tid;
        bool valid = idx < n;
        float t = valid ? tg[idx] : 0.f;
        bool flag = valid && (bucket_of(t) == b);
        unsigned vote = __ballot_sync(0xFFFFFFFFu, flag);
        int myrank = __popc(vote & ((1u << lane) - 1u));
        if (lane == 0) swcnt[wid] = __popc(vote);
        __syncthreads();
        int off = 0, tot = 0;
        #pragma unroll
        for (int w = 0; w < NWARP; w++) {
            int cw = swcnt[w];
            if (w < wid) off += cw;
            tot += cw;
        }
        if (flag) {
            int pos = base + running + off + myrank;
            g_ps[pos] = pr[idx];
            g_tt[pos] = t;
        }
        running += tot;
        __syncthreads();
    }
}

// ---------------------------------------------------------------------------
// 4) triangular pair kernel on bucket-ordered data with per-(thread, tile)
//    loop specialization, + last-block finalize.
// ---------------------------------------------------------------------------
__global__ __launch_bounds__(TPB) void pair_kernel(int n, int G, int T,
                                                   float* __restrict__ out) {
    const int b = blockIdx.x;
    double disc = (double)(2 * G + 1) * (double)(2 * G + 1) - 8.0 * (double)b;
    int r = (int)(((double)(2 * G + 1) - sqrt(disc)) * 0.5);
    while (r > 0 && (r * G - (r * (r - 1)) / 2) > b) --r;
    while (((r + 1) * G - ((r + 1) * r) / 2) <= b) ++r;
    const int c = r + (b - (r * G - (r * (r - 1)) / 2));
    const bool diag = (c == r);

    __shared__ float  sp[TILE];
    __shared__ float  stt[TILE];
    __shared__ float  swmin[NWARP], swmax[NWARP];
    __shared__ double swarp[NWARP];
    __shared__ bool   s_last;

    const int tid = threadIdx.x, lane = tid & 31, wid = tid >> 5;
    const int j0 = c * TILE;
    const int jcnt = min(TILE, n - j0);

    float tj = 0.f;
    bool  jv = (tid < jcnt);
    if (jv) {
        sp[tid]  = g_ps[j0 + tid];
        tj       = g_tt[j0 + tid];
        stt[tid] = tj;
    }
    float wmin = jv ? tj :  3.0e38f;
    float wmax = jv ? tj : -3.0e38f;
    #pragma unroll
    for (int o = 16; o > 0; o >>= 1) {
        wmin = fminf(wmin, __shfl_xor_sync(0xFFFFFFFFu, wmin, o));
        wmax = fmaxf(wmax, __shfl_xor_sync(0xFFFFFFFFu, wmax, o));
    }
    if (lane == 0) { swmin[wid] = wmin; swmax[wid] = wmax; }
    __syncthreads();

    float tmin_c =  3.0e38f, tmax_c = -3.0e38f;
    #pragma unroll
    for (int w = 0; w < NWARP; w++) {
        tmin_c = fminf(tmin_c, swmin[w]);
        tmax_c = fmaxf(tmax_c, swmax[w]);
    }

    const int  i  = r * TILE + tid;
    const bool vi = (i < n);
    const float p0 = vi ? g_ps[i] : 0.f;
    const float t0 = vi ? g_tt[i] : 0.f;

    float acch = 0.f, accm = 0.f;
    if (vi) {
        const int k0 = diag ? tid + 1 : 0;
        // exact bounds on dt = fl(t0 - tj) over the tile (fp32 sub monotone)
        const float dmin = t0 - tmax_c;
        const float dmax = t0 - tmin_c;

        if (dmin > MARGIN) {
            // every pair: dt > m  ->  max(m - dp, 0) = max(pj - (p0 - m), 0)
            const float d0 = p0 - MARGIN;
            float a0 = 0.f, a1 = 0.f;
            int k = k0;
            #pragma unroll 8
            for (; k + 1 < jcnt; k += 2) {
                a0 += fmaxf(sp[k]     - d0, 0.f);
                a1 += fmaxf(sp[k + 1] - d0, 0.f);
            }
            if (k < jcnt) a0 += fmaxf(sp[k] - d0, 0.f);
            acch = a0 + a1;
        } else if (dmax < -MARGIN) {
            // every pair: dt < -m  ->  max(m + dp, 0) = max((p0 + m) - pj, 0)
            const float c0 = p0 + MARGIN;
            float a0 = 0.f, a1 = 0.f;
            int k = k0;
            #pragma unroll 8
            for (; k + 1 < jcnt; k += 2) {
                a0 += fmaxf(c0 - sp[k],     0.f);
                a1 += fmaxf(c0 - sp[k + 1], 0.f);
            }
            if (k < jcnt) a0 += fmaxf(c0 - sp[k], 0.f);
            acch = a0 + a1;
        } else if (dmax <= MARGIN && dmin >= -MARGIN) {
            // every pair: |dt| <= m  ->  0.1 * |dp|  (0.1 hoisted)
            float a0 = 0.f, a1 = 0.f;
            int k = k0;
            #pragma unroll 8
            for (; k + 1 < jcnt; k += 2) {
                a0 += fabsf(p0 - sp[k]);
                a1 += fabsf(p0 - sp[k + 1]);
            }
            if (k < jcnt) a0 += fabsf(p0 - sp[k]);
            accm = a0 + a1;
        } else {
            // mixed: exact per-pair test (reference-identical predicates)
            #pragma unroll 4
            for (int k = k0; k < jcnt; k++) {
                float dp = p0 - sp[k];
                float dt = t0 - stt[k];
                float u  = __uint_as_float(__float_as_uint(dp) ^
                           (__float_as_uint(dt) & 0x80000000u));
                float h  = fmaxf(MARGIN - u, 0.0f);
                if (fabsf(dt) > MARGIN) acch += h;
                else                    accm += fabsf(dp);
            }
        }
    }

    double mine = (double)acch + 0.1 * (double)accm;
    #pragma unroll
    for (int o = 16; o > 0; o >>= 1)
        mine += __shfl_down_sync(0xFFFFFFFFu, mine, o);
    if (lane == 0) swarp[wid] = mine;
    __syncthreads();

    if (wid == 0) {
        double v = (lane < NWARP) ? swarp[lane] : 0.0;
        #pragma unroll
        for (int o = 4; o > 0; o >>= 1)
            v += __shfl_down_sync(0xFFFFFFFFu, v, o);
        if (lane == 0) atomicAdd(&g_rank_sum, v);
    }

    if (tid == 0) {
        __threadfence();
        unsigned int prev = atomicAdd(&g_done, 1u);
        s_last = (prev == (unsigned int)(T - 1));
    }
    __syncthreads();

    if (s_last && tid == 0) {
        double sm  = g_m[0], sp2 = g_m[1], st = g_m[2], st2 = g_m[3], sd2 = g_m[4];
        double nn = (double)n;
        double mse  = sd2 / nn;
        double pvar = (sp2 - sm * sm / nn) / (nn - 1.0);
        double tvar = (st2 - st * st / nn) / (nn - 1.0);
        double divl = fmax(tvar - pvar, 0.0);
        double pc   = nn * (nn - 1.0) * 0.5;
        double rank = g_rank_sum / pc;
        out[0] = (float)(0.1 * mse + 0.9 * rank + 0.1 * divl);
    }
}

extern "C" void kernel_launch(void* const* d_in, const int* in_sizes, int n_in,
                              void* d_out, int out_size) {
    const float* pred = (const float*)d_in[0];
    const float* targ = (const float*)d_in[1];
    int n = in_sizes[0];

    init_kernel<<<1, 128>>>();
    histmom_kernel<<<32, TPB>>>(pred, targ, n);
    prefix_kernel<<<1, 32>>>();
    scatter_kernel<<<NB, TPB>>>(pred, targ, n);

    int G = (n + TILE - 1) / TILE;
    int T = G * (G + 1) / 2;
    pair_kernel<<<T, TPB>>>(n, G, T, (float*)d_out);
}

// round 5
// speedup vs baseline: 1.2310x; 1.2310x over previous
#include <cuda_runtime.h>

#define MARGIN 0.2f
#define TPB   256
#define TILE  256
#define NWARP (TPB / 32)
#define NB    64
#define MAXN  16384
#define MAXBLK (MAXN / TPB)

__device__ double g_rank_sum;
__device__ double g_m[5];          // sum_p, sum_p2, sum_t, sum_t2, sum_diff2
__device__ unsigned int g_done;
__device__ int   g_bh[MAXBLK * NB];   // per-(chunk, bucket) counts -> offsets
__device__ int   g_bstart[NB + 1];    // global bucket starts (+ sentinel n)
__device__ int   g_btmin[NB];         // bucket t-min (float bits, t >= 0)
__device__ int   g_btmax[NB];         // bucket t-max (float bits)
__device__ float g_ps[MAXN];          // predictions, bucket-reordered
__device__ float g_tt[MAXN];          // targets, bucket-reordered

__device__ __forceinline__ int bucket_of(float t) {
    int b = (int)(t * (float)NB);
    return min(NB - 1, max(0, b));
}

// ---------------------------------------------------------------------------
// 0) zero / init all accumulators (graph-replayed)
// ---------------------------------------------------------------------------
__global__ void init_kernel(int nblk) {
    int i = blockIdx.x * blockDim.x + threadIdx.x;
    for (int q = i; q < nblk * NB; q += gridDim.x * blockDim.x) g_bh[q] = 0;
    if (i < NB) { g_btmin[i] = 0x7F7FFFFF; g_btmax[i] = 0; }
    if (i == NB)     g_rank_sum = 0.0;
    if (i == NB + 1) g_done = 0u;
    if (i >= NB + 2 && i < NB + 7) g_m[i - NB - 2] = 0.0;
}

// ---------------------------------------------------------------------------
// 1) per-chunk bucket histogram + bucket t-min/max + O(N) moments
//    block `blk` owns input chunk [blk*TPB, blk*TPB+TPB)
// ---------------------------------------------------------------------------
__global__ __launch_bounds__(TPB) void histmom_kernel(const float* __restrict__ pr,
                                                      const float* __restrict__ tg,
                                                      int n) {
    __shared__ int    shist[NB], smin[NB], smax[NB];
    __shared__ double smom[5][NWARP];
    const int tid = threadIdx.x, lane = tid & 31, wid = tid >> 5;
    const int blk = blockIdx.x;
    const int idx = blk * TPB + tid;

    for (int q = tid; q < NB; q += TPB) {
        shist[q] = 0; smin[q] = 0x7F7FFFFF; smax[q] = 0;
    }
    __syncthreads();

    double m[5] = {0, 0, 0, 0, 0};
    if (idx < n) {
        float p = pr[idx], t = tg[idx];
        int b = bucket_of(t);
        atomicAdd(&shist[b], 1);
        int tb = __float_as_int(t);          // t >= 0: int order == float order
        atomicMin(&smin[b], tb);
        atomicMax(&smax[b], tb);
        double pv = (double)p, tv = (double)t, d = pv - tv;
        m[0] = pv; m[1] = pv * pv; m[2] = tv; m[3] = tv * tv; m[4] = d * d;
    }
    #pragma unroll
    for (int q = 0; q < 5; q++) {
        #pragma unroll
        for (int o = 16; o > 0; o >>= 1)
            m[q] += __shfl_down_sync(0xFFFFFFFFu, m[q], o);
        if (lane == 0) smom[q][wid] = m[q];
    }
    __syncthreads();
    if (wid == 0) {
        #pragma unroll
        for (int q = 0; q < 5; q++) {
            double v = (lane < NWARP) ? smom[q][lane] : 0.0;
            #pragma unroll
            for (int o = 4; o > 0; o >>= 1)
                v += __shfl_down_sync(0xFFFFFFFFu, v, o);
            if (lane == 0) atomicAdd(&g_m[q], v);
        }
    }
    for (int q = tid; q < NB; q += TPB) {
        g_bh[blk * NB + q] = shist[q];
        if (smax[q]) {   // bucket touched by this chunk
            atomicMin(&g_btmin[q], smin[q]);
            atomicMax(&g_btmax[q], smax[q]);
        } else if (shist[q]) {  // touched, but t could be exactly 0.0
            atomicMin(&g_btmin[q], smin[q]);
            atomicMax(&g_btmax[q], smax[q]);
        }
    }
}

// ---------------------------------------------------------------------------
// 2) offsets: column prefix over chunks per bucket, then bucket bases.
//    single block, NB threads do the work.
// ---------------------------------------------------------------------------
__global__ void offsets_kernel(int n, int nblk) {
    __shared__ int tot[NB], base[NB];
    int b = threadIdx.x;
    if (b < NB) {
        int s = 0;
        for (int k = 0; k < nblk; k++) {
            int t = g_bh[k * NB + b];
            g_bh[k * NB + b] = s;
            s += t;
        }
        tot[b] = s;
    }
    __syncthreads();
    if (b == 0) {
        int s = 0;
        for (int q = 0; q < NB; q++) { base[q] = s; g_bstart[q] = s; s += tot[q]; }
        g_bstart[NB] = n;
    }
    __syncthreads();
    if (b < NB) {
        int bb = base[b];
        for (int k = 0; k < nblk; k++) g_bh[k * NB + b] += bb;
    }
}

// ---------------------------------------------------------------------------
// 3) scatter: block `blk` ranks only its own 256 elements (stable, O(TPB))
// ---------------------------------------------------------------------------
__global__ __launch_bounds__(TPB) void scatter_kernel(const float* __restrict__ pr,
                                                      const float* __restrict__ tg,
                                                      int n) {
    __shared__ int sb[TPB];
    const int tid = threadIdx.x;
    const int blk = blockIdx.x;
    const int idx = blk * TPB + tid;
    const bool valid = idx < n;
    float t = valid ? tg[idx] : 0.f;
    int myb = valid ? bucket_of(t) : -1;
    sb[tid] = myb;
    __syncthreads();
    if (valid) {
        int rank = 0;
        for (int j = 0; j < tid; j++) rank += (sb[j] == myb);
        int pos = g_bh[blk * NB + myb] + rank;
        g_ps[pos] = pr[idx];
        g_tt[pos] = t;
    }
}

// ---------------------------------------------------------------------------
// 4) triangular pair kernel, bucket-segmented specialization + finalize
// ---------------------------------------------------------------------------
__global__ __launch_bounds__(TPB) void pair_kernel(int n, int G, int T,
                                                   float* __restrict__ out) {
    const int b = blockIdx.x;
    double disc = (double)(2 * G + 1) * (double)(2 * G + 1) - 8.0 * (double)b;
    int r = (int)(((double)(2 * G + 1) - sqrt(disc)) * 0.5);
    while (r > 0 && (r * G - (r * (r - 1)) / 2) > b) --r;
    while (((r + 1) * G - ((r + 1) * r) / 2) <= b) ++r;
    const int c = r + (b - (r * G - (r * (r - 1)) / 2));
    const bool diag = (c == r);

    __shared__ float  sp[TILE];
    __shared__ float  stt[TILE];
    __shared__ int    sbs[NB + 1];
    __shared__ float  sbmin[NB], sbmax[NB];
    __shared__ double swarp[NWARP];
    __shared__ int    s_bf, s_bl;
    __shared__ bool   s_last;

    const int tid = threadIdx.x, lane = tid & 31, wid = tid >> 5;
    const int j0 = c * TILE;
    const int jcnt = min(TILE, n - j0);
    const int jend = j0 + jcnt;

    if (tid < jcnt) {
        sp[tid]  = g_ps[j0 + tid];
        stt[tid] = g_tt[j0 + tid];
    }
    if (tid < NB) {
        sbmin[tid] = __int_as_float(g_btmin[tid]);
        sbmax[tid] = __int_as_float(g_btmax[tid]);
    }
    if (tid < NB + 1) sbs[tid] = g_bstart[tid];
    __syncthreads();
    if (tid < NB) {
        // unique bucket containing j0 / jend-1 (empty buckets can't match)
        if (sbs[tid] <= j0 && j0 < sbs[tid + 1]) s_bf = tid;
        if (sbs[tid] < jend && jend <= sbs[tid + 1]) s_bl = tid;
    }
    __syncthreads();
    const int bf = s_bf, bl = s_bl;

    const int  i  = r * TILE + tid;
    const bool vi = (i < n);
    const float p0 = vi ? g_ps[i] : 0.f;
    const float t0 = vi ? g_tt[i] : 0.f;
    const int  k0 = diag ? tid + 1 : 0;

    float acch = 0.f, accm = 0.f;
    if (vi) {
        for (int bb = bf; bb <= bl; bb++) {
            int lo = max(sbs[bb] - j0, k0);
            int hi = min(sbs[bb + 1] - j0, jcnt);
            if (lo >= hi) continue;
            // exact classification by monotonicity of fp32 subtraction:
            const float dtmax = t0 - sbmin[bb];   // >= any fl(t0 - tj) in seg
            const float dtmin = t0 - sbmax[bb];   // <= any fl(t0 - tj) in seg

            if (dtmin > MARGIN) {
                // all dt > m: relu(m - dp) = relu(pj - (p0 - m))
                const float d0 = p0 - MARGIN;
                float a0 = 0.f, a1 = 0.f;
                int k = lo;
                #pragma unroll 4
                for (; k + 1 < hi; k += 2) {
                    a0 += fmaxf(sp[k]     - d0, 0.f);
                    a1 += fmaxf(sp[k + 1] - d0, 0.f);
                }
                if (k < hi) a0 += fmaxf(sp[k] - d0, 0.f);
                acch += a0 + a1;
            } else if (dtmax < -MARGIN) {
                // all dt < -m: relu(m + dp) = relu((p0 + m) - pj)
                const float c0 = p0 + MARGIN;
                float a0 = 0.f, a1 = 0.f;
                int k = lo;
                #pragma unroll 4
                for (; k + 1 < hi; k += 2) {
                    a0 += fmaxf(c0 - sp[k],     0.f);
                    a1 += fmaxf(c0 - sp[k + 1], 0.f);
                }
                if (k < hi) a0 += fmaxf(c0 - sp[k], 0.f);
                acch += a0 + a1;
            } else if (dtmax <= MARGIN && dtmin >= -MARGIN) {
                // all |dt| <= m: 0.1*|dp| (0.1 hoisted)
                float a0 = 0.f, a1 = 0.f;
                int k = lo;
                #pragma unroll 4
                for (; k + 1 < hi; k += 2) {
                    a0 += fabsf(p0 - sp[k]);
                    a1 += fabsf(p0 - sp[k + 1]);
                }
                if (k < hi) a0 += fabsf(p0 - sp[k]);
                accm += a0 + a1;
            } else {
                // boundary bucket: exact per-pair predicates
                #pragma unroll 4
                for (int k = lo; k < hi; k++) {
                    float dp = p0 - sp[k];
                    float dt = t0 - stt[k];
                    float u  = __uint_as_float(__float_as_uint(dp) ^
                               (__float_as_uint(dt) & 0x80000000u));
                    float h  = fmaxf(MARGIN - u, 0.0f);
                    if (fabsf(dt) > MARGIN) acch += h;
                    else                    accm += fabsf(dp);
                }
            }
        }
    }

    double mine = (double)acch + 0.1 * (double)accm;
    #pragma unroll
    for (int o = 16; o > 0; o >>= 1)
        mine += __shfl_down_sync(0xFFFFFFFFu, mine, o);
    if (lane == 0) swarp[wid] = mine;
    __syncthreads();

    if (wid == 0) {
        double v = (lane < NWARP) ? swarp[lane] : 0.0;
        #pragma unroll
        for (int o = 4; o > 0; o >>= 1)
            v += __shfl_down_sync(0xFFFFFFFFu, v, o);
        if (lane == 0) atomicAdd(&g_rank_sum, v);
    }

    if (tid == 0) {
        __threadfence();
        unsigned int prev = atomicAdd(&g_done, 1u);
        s_last = (prev == (unsigned int)(T - 1));
    }
    __syncthreads();

    if (s_last && tid == 0) {
        double sm  = g_m[0], sp2 = g_m[1], st = g_m[2], st2 = g_m[3], sd2 = g_m[4];
        double nn = (double)n;
        double mse  = sd2 / nn;
        double pvar = (sp2 - sm * sm / nn) / (nn - 1.0);
        double tvar = (st2 - st * st / nn) / (nn - 1.0);
        double divl = fmax(tvar - pvar, 0.0);
        double pc   = nn * (nn - 1.0) * 0.5;
        double rank = g_rank_sum / pc;
        out[0] = (float)(0.1 * mse + 0.9 * rank + 0.1 * divl);
    }
}

extern "C" void kernel_launch(void* const* d_in, const int* in_sizes, int n_in,
                              void* d_out, int out_size) {
    const float* pred = (const float*)d_in[0];
    const float* targ = (const float*)d_in[1];
    int n = in_sizes[0];
    int nblk = (n + TPB - 1) / TPB;

    init_kernel<<<16, TPB>>>(nblk);
    histmom_kernel<<<nblk, TPB>>>(pred, targ, n);
    offsets_kernel<<<1, NB>>>(n, nblk);
    scatter_kernel<<<nblk, TPB>>>(pred, targ, n);

    int G = (n + TILE - 1) / TILE;
    int T = G * (G + 1) / 2;
    pair_kernel<<<T, TPB>>>(n, G, T, (float*)d_out);
}